// round 12
// baseline (speedup 1.0000x reference)
#include <cuda_runtime.h>
#include <cuda_bf16.h>
#include <math.h>
#include <stdint.h>

#define NN 100000
#define NE 1600000
#define DD 128
#define CC 64
#define NL 4

// ---------------- scratch (device globals: allocation-free) ----------------
__device__ float g_h0[NN * DD];
__device__ float g_hA[NN * DD];
__device__ float g_hB[NN * DD];
__device__ int   g_rowptr[NN + 1];
__device__ int   g_cursor[NN];
__device__ int   g_col[NE];
__device__ float g_val[NE];
__device__ int   g_bsum[128];

// ---------------- packed f32x2 helpers ----------------
__device__ __forceinline__ uint64_t bcast2(float v) {
    uint64_t r;
    asm("mov.b64 %0, {%1, %1};" : "=l"(r) : "f"(v));
    return r;
}
__device__ __forceinline__ uint64_t fma2(uint64_t a, uint64_t b, uint64_t c) {
    uint64_t d;
    asm("fma.rn.f32x2 %0, %1, %2, %3;" : "=l"(d) : "l"(a), "l"(b), "l"(c));
    return d;
}
__device__ __forceinline__ float2 unpack2(uint64_t v) {
    float2 f;
    asm("mov.b64 {%0, %1}, %2;" : "=f"(f.x), "=f"(f.y) : "l"(v));
    return f;
}

// ---------------- CSR build ----------------
__global__ void k_zero_rowptr() {
    int i = blockIdx.x * blockDim.x + threadIdx.x;
    if (i <= NN) g_rowptr[i] = 0;
}
__global__ void k_hist(const int* __restrict__ edst) {
    int i = blockIdx.x * blockDim.x + threadIdx.x;
    if (i < NE) atomicAdd(&g_rowptr[edst[i] + 1], 1);
}
__global__ void k_scan1() {
    __shared__ int sh[2][1024];
    int t = threadIdx.x;
    int i = blockIdx.x * 1024 + t;
    int v = (i <= NN) ? g_rowptr[i] : 0;
    sh[0][t] = v;
    __syncthreads();
    int p = 0;
    #pragma unroll
    for (int off = 1; off < 1024; off <<= 1) {
        int q = p ^ 1;
        int add = (t >= off) ? sh[p][t - off] : 0;
        sh[q][t] = sh[p][t] + add;
        __syncthreads();
        p = q;
    }
    if (i <= NN) g_rowptr[i] = sh[p][t];
    if (t == 1023) g_bsum[blockIdx.x] = sh[p][1023];
}
__global__ void k_scan2(int nb) {
    __shared__ int sh[128];
    int t = threadIdx.x;
    if (t < nb) sh[t] = g_bsum[t];
    __syncthreads();
    if (t == 0) {
        int s = 0;
        for (int b = 0; b < nb; b++) { s += sh[b]; sh[b] = s; }
    }
    __syncthreads();
    if (t < nb) g_bsum[t] = sh[t];
}
__global__ void k_scan3() {
    int t = threadIdx.x;
    int i = blockIdx.x * 1024 + t;
    if (i <= NN) {
        int v = g_rowptr[i];
        if (blockIdx.x > 0) v += g_bsum[blockIdx.x - 1];
        g_rowptr[i] = v;
        if (i < NN) g_cursor[i] = v;
    }
}
__global__ void k_fill(const int* __restrict__ esrc, const int* __restrict__ edst,
                       const float* __restrict__ ew) {
    int i = blockIdx.x * blockDim.x + threadIdx.x;
    if (i < NE) {
        int d = edst[i];
        int p = atomicAdd(&g_cursor[d], 1);
        g_col[p] = esrc[i];
        g_val[p] = ew[i];
    }
}

// ---------------- input GEMM: out = relu(A@W + bias) ----------------
__global__ void __launch_bounds__(256, 2) k_gemm_in(
    const float* __restrict__ A, const float* __restrict__ W,
    const float* __restrict__ bias, float* __restrict__ out)
{
    extern __shared__ float sh[];
    float* Wsh = sh;                 // 128*128
    float* Ssh = sh + DD * DD;       // 64*128
    int t = threadIdx.x;

    float4* Wsh4 = (float4*)Wsh;
    const float4* W4 = (const float4*)W;
    #pragma unroll
    for (int i = 0; i < 16; i++) Wsh4[t + i * 256] = W4[t + i * 256];

    int base = blockIdx.x * 64;
    float4* Ssh4 = (float4*)Ssh;
    const float4* A4 = (const float4*)A;
    #pragma unroll
    for (int i = 0; i < 8; i++) {
        int f = t + i * 256;
        int row = base + (f >> 5);
        Ssh4[f] = (row < NN) ? A4[base * 32 + f] : make_float4(0.f, 0.f, 0.f, 0.f);
    }
    __syncthreads();

    int warp = t >> 5, lane = t & 31;
    int srow = warp * 8;

    uint64_t acc[8][2];
    #pragma unroll
    for (int r = 0; r < 8; r++) { acc[r][0] = 0ull; acc[r][1] = 0ull; }

    const ulonglong2* Wshp = (const ulonglong2*)Wsh;
    #pragma unroll 4
    for (int k = 0; k < DD; k += 2) {
        ulonglong2 wa = Wshp[k * 32 + lane];
        ulonglong2 wb = Wshp[(k + 1) * 32 + lane];
        #pragma unroll
        for (int r = 0; r < 8; r++) {
            float2 sv = *(const float2*)&Ssh[(srow + r) * DD + k];
            uint64_t s0 = bcast2(sv.x);
            uint64_t s1 = bcast2(sv.y);
            acc[r][0] = fma2(s0, wa.x, acc[r][0]);
            acc[r][1] = fma2(s0, wa.y, acc[r][1]);
            acc[r][0] = fma2(s1, wb.x, acc[r][0]);
            acc[r][1] = fma2(s1, wb.y, acc[r][1]);
        }
    }

    const float4* b4 = (const float4*)bias;
    float4 b = b4[lane];
    #pragma unroll
    for (int r = 0; r < 8; r++) {
        int row = base + srow + r;
        if (row < NN) {
            float2 a01 = unpack2(acc[r][0]);
            float2 a23 = unpack2(acc[r][1]);
            float4 o;
            o.x = fmaxf(a01.x + b.x, 0.f);
            o.y = fmaxf(a01.y + b.y, 0.f);
            o.z = fmaxf(a23.x + b.z, 0.f);
            o.w = fmaxf(a23.y + b.w, 0.f);
            ((float4*)out)[row * 32 + lane] = o;
        }
    }
}

// ---------------- fused layer: SpMM + GEMM ----------------
// sup = 0.9*(Adj@hin) + 0.1*h0  (built in smem, 64-row tile)
// out = relu(c0*(sup@W) + c1*sup + hin)
__global__ void __launch_bounds__(256, 2) k_layer(
    const float* __restrict__ hin, const float* __restrict__ W,
    float* __restrict__ out, float c0, float c1)
{
    extern __shared__ float sh[];
    float* Wsh = sh;                 // 128*128 = 64KB
    float* Ssh = sh + DD * DD;       // 64*128  = 32KB (sup tile)
    int t = threadIdx.x;
    int warp = t >> 5, lane = t & 31;
    int base = blockIdx.x * 64;

    // load W
    float4* Wsh4 = (float4*)Wsh;
    const float4* W4 = (const float4*)W;
    #pragma unroll
    for (int i = 0; i < 16; i++) Wsh4[t + i * 256] = W4[t + i * 256];

    // SpMM phase: warp w builds rows [base + w*8, base + w*8 + 8)
    float4* Ssh4 = (float4*)Ssh;
    const float4* h4 = (const float4*)hin;
    const float4* h04 = (const float4*)g_h0;
    #pragma unroll 1
    for (int rr = 0; rr < 8; rr++) {
        int lrow = warp * 8 + rr;
        int row = base + lrow;
        float4 sup = make_float4(0.f, 0.f, 0.f, 0.f);
        if (row < NN) {
            int s = g_rowptr[row], e = g_rowptr[row + 1];
            float4 a0 = make_float4(0.f, 0.f, 0.f, 0.f);
            float4 a1 = make_float4(0.f, 0.f, 0.f, 0.f);
            int i = s;
            for (; i + 2 <= e; i += 2) {
                int c0i = __ldg(&g_col[i]);
                int c1i = __ldg(&g_col[i + 1]);
                float w0 = __ldg(&g_val[i]);
                float w1 = __ldg(&g_val[i + 1]);
                float4 v0 = h4[c0i * 32 + lane];
                float4 v1 = h4[c1i * 32 + lane];
                a0.x += w0 * v0.x; a0.y += w0 * v0.y; a0.z += w0 * v0.z; a0.w += w0 * v0.w;
                a1.x += w1 * v1.x; a1.y += w1 * v1.y; a1.z += w1 * v1.z; a1.w += w1 * v1.w;
            }
            if (i < e) {
                int c = __ldg(&g_col[i]);
                float w = __ldg(&g_val[i]);
                float4 v = h4[c * 32 + lane];
                a0.x += w * v.x; a0.y += w * v.y; a0.z += w * v.z; a0.w += w * v.w;
            }
            float4 z = h04[row * 32 + lane];
            sup.x = 0.9f * (a0.x + a1.x) + 0.1f * z.x;
            sup.y = 0.9f * (a0.y + a1.y) + 0.1f * z.y;
            sup.z = 0.9f * (a0.z + a1.z) + 0.1f * z.z;
            sup.w = 0.9f * (a0.w + a1.w) + 0.1f * z.w;
        }
        Ssh4[lrow * 32 + lane] = sup;
    }
    __syncthreads();

    // GEMM phase: 8 rows/warp, f32x2 accumulators
    int srow = warp * 8;
    uint64_t acc[8][2];
    #pragma unroll
    for (int r = 0; r < 8; r++) { acc[r][0] = 0ull; acc[r][1] = 0ull; }

    const ulonglong2* Wshp = (const ulonglong2*)Wsh;
    #pragma unroll 4
    for (int k = 0; k < DD; k += 2) {
        ulonglong2 wa = Wshp[k * 32 + lane];
        ulonglong2 wb = Wshp[(k + 1) * 32 + lane];
        #pragma unroll
        for (int r = 0; r < 8; r++) {
            float2 sv = *(const float2*)&Ssh[(srow + r) * DD + k];
            uint64_t s0 = bcast2(sv.x);
            uint64_t s1 = bcast2(sv.y);
            acc[r][0] = fma2(s0, wa.x, acc[r][0]);
            acc[r][1] = fma2(s0, wa.y, acc[r][1]);
            acc[r][0] = fma2(s1, wb.x, acc[r][0]);
            acc[r][1] = fma2(s1, wb.y, acc[r][1]);
        }
    }

    // epilogue: out = relu(c0*acc + c1*sup + hin)
    #pragma unroll
    for (int r = 0; r < 8; r++) {
        int row = base + srow + r;
        if (row < NN) {
            float2 a01 = unpack2(acc[r][0]);
            float2 a23 = unpack2(acc[r][1]);
            float4 s4 = Ssh4[(srow + r) * 32 + lane];
            float4 h = h4[row * 32 + lane];
            float4 o;
            o.x = fmaxf(c0 * a01.x + c1 * s4.x + h.x, 0.f);
            o.y = fmaxf(c0 * a01.y + c1 * s4.y + h.y, 0.f);
            o.z = fmaxf(c0 * a23.x + c1 * s4.z + h.z, 0.f);
            o.w = fmaxf(c0 * a23.y + c1 * s4.w + h.w, 0.f);
            ((float4*)out)[row * 32 + lane] = o;
        }
    }
}

// ---------------- output head: logits = h@w_out + b_out -> log_softmax ----------------
__global__ void k_out(const float* __restrict__ hin, const float* __restrict__ wout,
                      const float* __restrict__ bout, float* __restrict__ out)
{
    __shared__ float Wsh[DD * CC];   // 32KB
    __shared__ float Hsh[8][DD];     // 4KB
    int t = threadIdx.x;

    float4* Wsh4 = (float4*)Wsh;
    const float4* w4 = (const float4*)wout;
    #pragma unroll
    for (int i = 0; i < 8; i++) Wsh4[t + i * 256] = w4[t + i * 256];
    __syncthreads();

    int warp = t >> 5, lane = t & 31;
    int row = blockIdx.x * 8 + warp;
    if (row >= NN) return;

    ((float4*)Hsh[warp])[lane] = ((const float4*)hin)[row * 32 + lane];
    __syncwarp();

    uint64_t accp = *(const uint64_t*)&bout[2 * lane];
    const uint64_t* Wshp = (const uint64_t*)Wsh;
    #pragma unroll 4
    for (int k = 0; k < DD; k++) {
        float hv = Hsh[warp][k];
        accp = fma2(bcast2(hv), Wshp[k * 32 + lane], accp);
    }
    float2 a = unpack2(accp);
    float a0 = a.x, a1 = a.y;

    float m = fmaxf(a0, a1);
    #pragma unroll
    for (int off = 16; off; off >>= 1) m = fmaxf(m, __shfl_xor_sync(0xffffffffu, m, off));
    float se = expf(a0 - m) + expf(a1 - m);
    #pragma unroll
    for (int off = 16; off; off >>= 1) se += __shfl_xor_sync(0xffffffffu, se, off);
    float lse = m + logf(se);

    out[row * 64 + 2 * lane]     = a0 - lse;
    out[row * 64 + 2 * lane + 1] = a1 - lse;
}

// ---------------- launch ----------------
extern "C" void kernel_launch(void* const* d_in, const int* in_sizes, int n_in,
                              void* d_out, int out_size)
{
    const float* x     = (const float*)d_in[0];
    const int*   esrc  = (const int*)  d_in[1];
    const int*   edst  = (const int*)  d_in[2];
    const float* ew    = (const float*)d_in[3];
    const float* w_in  = (const float*)d_in[4];
    const float* b_in  = (const float*)d_in[5];
    const float* gcn_w = (const float*)d_in[6];
    const float* w_out = (const float*)d_in[7];
    const float* b_out = (const float*)d_in[8];
    float* out = (float*)d_out;

    const int SMEM = (DD * DD + 64 * DD) * (int)sizeof(float); // 98304
    cudaFuncSetAttribute(k_gemm_in, cudaFuncAttributeMaxDynamicSharedMemorySize, SMEM);
    cudaFuncSetAttribute(k_layer,   cudaFuncAttributeMaxDynamicSharedMemorySize, SMEM);

    void *ph0v, *phAv, *phBv;
    cudaGetSymbolAddress(&ph0v, g_h0);
    cudaGetSymbolAddress(&phAv, g_hA);
    cudaGetSymbolAddress(&phBv, g_hB);
    float* ph0 = (float*)ph0v;
    float* phA = (float*)phAv;
    float* phB = (float*)phBv;

    const int NB = (NN + 1 + 1023) / 1024; // 98

    // CSR build
    k_zero_rowptr<<<(NN + 1 + 255) / 256, 256>>>();
    k_hist<<<(NE + 255) / 256, 256>>>(edst);
    k_scan1<<<NB, 1024>>>();
    k_scan2<<<1, 128>>>(NB);
    k_scan3<<<NB, 1024>>>();
    k_fill<<<(NE + 255) / 256, 256>>>(esrc, edst, ew);

    const int GB = (NN + 63) / 64;   // 1563 blocks
    const int OB = NN / 8;           // 12500 head blocks

    // h0 = relu(x @ w_in + b_in)
    k_gemm_in<<<GB, 256, SMEM>>>(x, w_in, b_in, ph0);

    float theta[NL];
    for (int l = 0; l < NL; l++) theta[l] = logf(0.5f / (float)(l + 2) + 1.0f);

    for (int l = 0; l < NL; l++) {
        float* hin  = (l == 0) ? ph0 : ((l & 1) ? phA : phB);
        float* hout = (l & 1) ? phB : phA;
        k_layer<<<GB, 256, SMEM>>>(hin, gcn_w + l * DD * DD, hout,
                                   theta[l], 1.0f - theta[l]);
    }

    // final h in g_hB (l=3 -> hout=phB)
    k_out<<<OB, 256>>>(phB, w_out, b_out, out);
}

// round 13
// speedup vs baseline: 1.1150x; 1.1150x over previous
#include <cuda_runtime.h>
#include <cuda_bf16.h>
#include <math.h>
#include <stdint.h>

#define NN 100000
#define NE 1600000
#define DD 128
#define CC 64
#define NL 4

// ---------------- scratch (device globals: allocation-free) ----------------
__device__ float g_h0[NN * DD];
__device__ float g_hA[NN * DD];
__device__ float g_hB[NN * DD];
__device__ float g_sup[NN * DD];
__device__ int   g_rowptr[NN + 1];
__device__ int   g_cursor[NN];
__device__ int2  g_edge[NE];        // packed (col, val-as-int)
__device__ int   g_bsum[128];

// ---------------- packed f32x2 helpers ----------------
__device__ __forceinline__ uint64_t bcast2(float v) {
    uint64_t r;
    asm("mov.b64 %0, {%1, %1};" : "=l"(r) : "f"(v));
    return r;
}
__device__ __forceinline__ uint64_t fma2(uint64_t a, uint64_t b, uint64_t c) {
    uint64_t d;
    asm("fma.rn.f32x2 %0, %1, %2, %3;" : "=l"(d) : "l"(a), "l"(b), "l"(c));
    return d;
}
__device__ __forceinline__ float2 unpack2(uint64_t v) {
    float2 f;
    asm("mov.b64 {%0, %1}, %2;" : "=f"(f.x), "=f"(f.y) : "l"(v));
    return f;
}

// ---------------- CSR build ----------------
__global__ void k_zero_rowptr() {
    int i = blockIdx.x * blockDim.x + threadIdx.x;
    if (i <= NN) g_rowptr[i] = 0;
}
__global__ void k_hist(const int* __restrict__ edst) {
    int i = blockIdx.x * blockDim.x + threadIdx.x;
    if (i < NE) atomicAdd(&g_rowptr[__ldcs(&edst[i]) + 1], 1);
}
__global__ void k_scan1() {
    __shared__ int sh[2][1024];
    int t = threadIdx.x;
    int i = blockIdx.x * 1024 + t;
    int v = (i <= NN) ? g_rowptr[i] : 0;
    sh[0][t] = v;
    __syncthreads();
    int p = 0;
    #pragma unroll
    for (int off = 1; off < 1024; off <<= 1) {
        int q = p ^ 1;
        int add = (t >= off) ? sh[p][t - off] : 0;
        sh[q][t] = sh[p][t] + add;
        __syncthreads();
        p = q;
    }
    if (i <= NN) g_rowptr[i] = sh[p][t];
    if (t == 1023) g_bsum[blockIdx.x] = sh[p][1023];
}
__global__ void k_scan2(int nb) {
    __shared__ int sh[128];
    int t = threadIdx.x;
    if (t < nb) sh[t] = g_bsum[t];
    __syncthreads();
    if (t == 0) {
        int s = 0;
        for (int b = 0; b < nb; b++) { s += sh[b]; sh[b] = s; }
    }
    __syncthreads();
    if (t < nb) g_bsum[t] = sh[t];
}
__global__ void k_scan3() {
    int t = threadIdx.x;
    int i = blockIdx.x * 1024 + t;
    if (i <= NN) {
        int v = g_rowptr[i];
        if (blockIdx.x > 0) v += g_bsum[blockIdx.x - 1];
        g_rowptr[i] = v;
        if (i < NN) g_cursor[i] = v;
    }
}
__global__ void k_fill(const int* __restrict__ esrc, const int* __restrict__ edst,
                       const float* __restrict__ ew) {
    int i = blockIdx.x * blockDim.x + threadIdx.x;
    if (i < NE) {
        int d = __ldcs(&edst[i]);
        int p = atomicAdd(&g_cursor[d], 1);
        g_edge[p] = make_int2(__ldcs(&esrc[i]), __float_as_int(__ldcs(&ew[i])));
    }
}

// ---------------- SpMM: g_sup = 0.9*Adj@hin + 0.1*h0, warp-per-row, 4-way MLP ----
__global__ void k_spmm(const float* __restrict__ hin) {
    int gw = (blockIdx.x * blockDim.x + threadIdx.x) >> 5;
    int lane = threadIdx.x & 31;
    if (gw >= NN) return;
    int s = g_rowptr[gw], e = g_rowptr[gw + 1];
    const float4* h4 = (const float4*)hin;
    float4 a0 = make_float4(0.f, 0.f, 0.f, 0.f);
    float4 a1 = make_float4(0.f, 0.f, 0.f, 0.f);
    int i = s;
    for (; i + 4 <= e; i += 4) {
        int2 e0 = __ldcs(&g_edge[i]);
        int2 e1 = __ldcs(&g_edge[i + 1]);
        int2 e2 = __ldcs(&g_edge[i + 2]);
        int2 e3 = __ldcs(&g_edge[i + 3]);
        float4 v0 = h4[e0.x * 32 + lane];
        float4 v1 = h4[e1.x * 32 + lane];
        float4 v2 = h4[e2.x * 32 + lane];
        float4 v3 = h4[e3.x * 32 + lane];
        float w0 = __int_as_float(e0.y), w1 = __int_as_float(e1.y);
        float w2 = __int_as_float(e2.y), w3 = __int_as_float(e3.y);
        a0.x += w0 * v0.x; a0.y += w0 * v0.y; a0.z += w0 * v0.z; a0.w += w0 * v0.w;
        a1.x += w1 * v1.x; a1.y += w1 * v1.y; a1.z += w1 * v1.z; a1.w += w1 * v1.w;
        a0.x += w2 * v2.x; a0.y += w2 * v2.y; a0.z += w2 * v2.z; a0.w += w2 * v2.w;
        a1.x += w3 * v3.x; a1.y += w3 * v3.y; a1.z += w3 * v3.z; a1.w += w3 * v3.w;
    }
    for (; i < e; i++) {
        int2 e0 = __ldcs(&g_edge[i]);
        float w = __int_as_float(e0.y);
        float4 v = h4[e0.x * 32 + lane];
        a0.x += w * v.x; a0.y += w * v.y; a0.z += w * v.z; a0.w += w * v.w;
    }
    a0.x += a1.x; a0.y += a1.y; a0.z += a1.z; a0.w += a1.w;
    const float4* h04 = (const float4*)g_h0;
    float4 z = __ldg(&h04[gw * 32 + lane]);
    float4 r;
    r.x = 0.9f * a0.x + 0.1f * z.x;
    r.y = 0.9f * a0.y + 0.1f * z.y;
    r.z = 0.9f * a0.z + 0.1f * z.z;
    r.w = 0.9f * a0.w + 0.1f * z.w;
    __stcs(&((float4*)g_sup)[gw * 32 + lane], r);
}

// ---------------- GEMM: out = relu(c0*(A@W) + c1*A + hprev + bias) ----------------
__global__ void __launch_bounds__(256, 2) k_gemm(
    const float* __restrict__ A, const float* __restrict__ W,
    const float* __restrict__ hprev, const float* __restrict__ bias,
    float* __restrict__ out, float c0, float c1)
{
    extern __shared__ float sh[];
    float* Wsh = sh;                 // 128*128
    float* Ssh = sh + DD * DD;       // 64*128
    int t = threadIdx.x;

    float4* Wsh4 = (float4*)Wsh;
    const float4* W4 = (const float4*)W;
    #pragma unroll
    for (int i = 0; i < 16; i++) Wsh4[t + i * 256] = W4[t + i * 256];

    int base = blockIdx.x * 64;
    float4* Ssh4 = (float4*)Ssh;
    const float4* A4 = (const float4*)A;
    #pragma unroll
    for (int i = 0; i < 8; i++) {
        int f = t + i * 256;
        int row = base + (f >> 5);
        Ssh4[f] = (row < NN) ? A4[base * 32 + f] : make_float4(0.f, 0.f, 0.f, 0.f);
    }
    __syncthreads();

    int warp = t >> 5, lane = t & 31;
    int srow = warp * 8;

    uint64_t acc[8][2];
    #pragma unroll
    for (int r = 0; r < 8; r++) { acc[r][0] = 0ull; acc[r][1] = 0ull; }

    const ulonglong2* Wshp = (const ulonglong2*)Wsh;
    #pragma unroll 4
    for (int k = 0; k < DD; k += 2) {
        ulonglong2 wa = Wshp[k * 32 + lane];
        ulonglong2 wb = Wshp[(k + 1) * 32 + lane];
        #pragma unroll
        for (int r = 0; r < 8; r++) {
            float2 sv = *(const float2*)&Ssh[(srow + r) * DD + k];
            uint64_t s0 = bcast2(sv.x);
            uint64_t s1 = bcast2(sv.y);
            acc[r][0] = fma2(s0, wa.x, acc[r][0]);
            acc[r][1] = fma2(s0, wa.y, acc[r][1]);
            acc[r][0] = fma2(s1, wb.x, acc[r][0]);
            acc[r][1] = fma2(s1, wb.y, acc[r][1]);
        }
    }

    const float4* hp4 = (const float4*)hprev;
    const float4* b4 = (const float4*)bias;
    #pragma unroll
    for (int r = 0; r < 8; r++) {
        int row = base + srow + r;
        if (row < NN) {
            float2 a01 = unpack2(acc[r][0]);
            float2 a23 = unpack2(acc[r][1]);
            float4 s4 = Ssh4[(srow + r) * 32 + lane];
            float4 o;
            o.x = c0 * a01.x + c1 * s4.x;
            o.y = c0 * a01.y + c1 * s4.y;
            o.z = c0 * a23.x + c1 * s4.z;
            o.w = c0 * a23.y + c1 * s4.w;
            if (hprev) {
                float4 h = hp4[row * 32 + lane];
                o.x += h.x; o.y += h.y; o.z += h.z; o.w += h.w;
            }
            if (bias) {
                float4 b = b4[lane];
                o.x += b.x; o.y += b.y; o.z += b.z; o.w += b.w;
            }
            o.x = fmaxf(o.x, 0.f); o.y = fmaxf(o.y, 0.f);
            o.z = fmaxf(o.z, 0.f); o.w = fmaxf(o.w, 0.f);
            ((float4*)out)[row * 32 + lane] = o;
        }
    }
}

// ---------------- output head: logits = h@w_out + b_out -> log_softmax ----------------
__global__ void k_out(const float* __restrict__ hin, const float* __restrict__ wout,
                      const float* __restrict__ bout, float* __restrict__ out)
{
    __shared__ float Wsh[DD * CC];   // 32KB
    __shared__ float Hsh[8][DD];     // 4KB
    int t = threadIdx.x;

    float4* Wsh4 = (float4*)Wsh;
    const float4* w4 = (const float4*)wout;
    #pragma unroll
    for (int i = 0; i < 8; i++) Wsh4[t + i * 256] = w4[t + i * 256];
    __syncthreads();

    int warp = t >> 5, lane = t & 31;
    int row = blockIdx.x * 8 + warp;
    if (row >= NN) return;

    ((float4*)Hsh[warp])[lane] = ((const float4*)hin)[row * 32 + lane];
    __syncwarp();

    uint64_t accp = *(const uint64_t*)&bout[2 * lane];
    const uint64_t* Wshp = (const uint64_t*)Wsh;
    #pragma unroll 4
    for (int k = 0; k < DD; k++) {
        float hv = Hsh[warp][k];
        accp = fma2(bcast2(hv), Wshp[k * 32 + lane], accp);
    }
    float2 a = unpack2(accp);
    float a0 = a.x, a1 = a.y;

    float m = fmaxf(a0, a1);
    #pragma unroll
    for (int off = 16; off; off >>= 1) m = fmaxf(m, __shfl_xor_sync(0xffffffffu, m, off));
    float se = expf(a0 - m) + expf(a1 - m);
    #pragma unroll
    for (int off = 16; off; off >>= 1) se += __shfl_xor_sync(0xffffffffu, se, off);
    float lse = m + logf(se);

    out[row * 64 + 2 * lane]     = a0 - lse;
    out[row * 64 + 2 * lane + 1] = a1 - lse;
}

// ---------------- launch ----------------
extern "C" void kernel_launch(void* const* d_in, const int* in_sizes, int n_in,
                              void* d_out, int out_size)
{
    const float* x     = (const float*)d_in[0];
    const int*   esrc  = (const int*)  d_in[1];
    const int*   edst  = (const int*)  d_in[2];
    const float* ew    = (const float*)d_in[3];
    const float* w_in  = (const float*)d_in[4];
    const float* b_in  = (const float*)d_in[5];
    const float* gcn_w = (const float*)d_in[6];
    const float* w_out = (const float*)d_in[7];
    const float* b_out = (const float*)d_in[8];
    float* out = (float*)d_out;

    const int GEMM_SMEM = (DD * DD + 64 * DD) * (int)sizeof(float); // 98304
    cudaFuncSetAttribute(k_gemm, cudaFuncAttributeMaxDynamicSharedMemorySize, GEMM_SMEM);

    void *ph0v, *phAv, *phBv, *psupv;
    cudaGetSymbolAddress(&ph0v, g_h0);
    cudaGetSymbolAddress(&phAv, g_hA);
    cudaGetSymbolAddress(&phBv, g_hB);
    cudaGetSymbolAddress(&psupv, g_sup);
    float* ph0 = (float*)ph0v;
    float* phA = (float*)phAv;
    float* phB = (float*)phBv;
    float* psup = (float*)psupv;

    const int NB = (NN + 1 + 1023) / 1024; // 98

    // CSR build
    k_zero_rowptr<<<(NN + 1 + 255) / 256, 256>>>();
    k_hist<<<(NE + 255) / 256, 256>>>(edst);
    k_scan1<<<NB, 1024>>>();
    k_scan2<<<1, 128>>>(NB);
    k_scan3<<<NB, 1024>>>();
    k_fill<<<(NE + 255) / 256, 256>>>(esrc, edst, ew);

    const int GB = (NN + 63) / 64;   // 1563 GEMM blocks
    const int SB = NN / 8;           // 12500 warp-per-row blocks

    // h0 = relu(x @ w_in + b_in)
    k_gemm<<<GB, 256, GEMM_SMEM>>>(x, w_in, nullptr, b_in, ph0, 1.0f, 0.0f);

    float theta[NL];
    for (int l = 0; l < NL; l++) theta[l] = logf(0.5f / (float)(l + 2) + 1.0f);

    for (int l = 0; l < NL; l++) {
        float* hin  = (l == 0) ? ph0 : ((l & 1) ? phA : phB);
        float* hout = (l & 1) ? phB : phA;
        k_spmm<<<SB, 256>>>(hin);                       // g_sup = 0.9*Adj@hin + 0.1*h0
        k_gemm<<<GB, 256, GEMM_SMEM>>>(psup, gcn_w + l * DD * DD, hin, nullptr,
                                       hout, theta[l], 1.0f - theta[l]);
    }

    // final h in g_hB (l=3 -> hout=phB)
    k_out<<<SB, 256>>>(phB, w_out, b_out, out);
}

// round 14
// speedup vs baseline: 1.1325x; 1.0156x over previous
#include <cuda_runtime.h>
#include <cuda_bf16.h>
#include <math.h>
#include <stdint.h>

#define NN 100000
#define NE 1600000
#define DD 128
#define CC 64
#define NL 4
#define STP 70   // padded row length of transposed S tile (floats)

// ---------------- scratch (device globals: allocation-free) ----------------
__device__ float g_h0[NN * DD];
__device__ float g_hA[NN * DD];
__device__ float g_hB[NN * DD];
__device__ float g_sup[NN * DD];
__device__ int   g_rowptr[NN + 1];
__device__ int   g_cursor[NN];
__device__ int2  g_edge[NE];        // packed (col, val-as-int)
__device__ int   g_bsum[128];

// ---------------- packed f32x2 helpers ----------------
__device__ __forceinline__ uint64_t bcast2(float v) {
    uint64_t r;
    asm("mov.b64 %0, {%1, %1};" : "=l"(r) : "f"(v));
    return r;
}
__device__ __forceinline__ uint64_t fma2(uint64_t a, uint64_t b, uint64_t c) {
    uint64_t d;
    asm("fma.rn.f32x2 %0, %1, %2, %3;" : "=l"(d) : "l"(a), "l"(b), "l"(c));
    return d;
}
__device__ __forceinline__ float2 unpack2(uint64_t v) {
    float2 f;
    asm("mov.b64 {%0, %1}, %2;" : "=f"(f.x), "=f"(f.y) : "l"(v));
    return f;
}

// ---------------- CSR build ----------------
__global__ void k_zero_rowptr() {
    int i = blockIdx.x * blockDim.x + threadIdx.x;
    if (i <= NN) g_rowptr[i] = 0;
}
__global__ void k_hist(const int* __restrict__ edst) {
    int i = blockIdx.x * blockDim.x + threadIdx.x;
    if (i < NE) atomicAdd(&g_rowptr[__ldcs(&edst[i]) + 1], 1);
}
__global__ void k_scan1() {
    __shared__ int sh[2][1024];
    int t = threadIdx.x;
    int i = blockIdx.x * 1024 + t;
    int v = (i <= NN) ? g_rowptr[i] : 0;
    sh[0][t] = v;
    __syncthreads();
    int p = 0;
    #pragma unroll
    for (int off = 1; off < 1024; off <<= 1) {
        int q = p ^ 1;
        int add = (t >= off) ? sh[p][t - off] : 0;
        sh[q][t] = sh[p][t] + add;
        __syncthreads();
        p = q;
    }
    if (i <= NN) g_rowptr[i] = sh[p][t];
    if (t == 1023) g_bsum[blockIdx.x] = sh[p][1023];
}
__global__ void k_scan2(int nb) {
    __shared__ int sh[128];
    int t = threadIdx.x;
    if (t < nb) sh[t] = g_bsum[t];
    __syncthreads();
    if (t == 0) {
        int s = 0;
        for (int b = 0; b < nb; b++) { s += sh[b]; sh[b] = s; }
    }
    __syncthreads();
    if (t < nb) g_bsum[t] = sh[t];
}
__global__ void k_scan3() {
    int t = threadIdx.x;
    int i = blockIdx.x * 1024 + t;
    if (i <= NN) {
        int v = g_rowptr[i];
        if (blockIdx.x > 0) v += g_bsum[blockIdx.x - 1];
        g_rowptr[i] = v;
        if (i < NN) g_cursor[i] = v;
    }
}
__global__ void k_fill(const int* __restrict__ esrc, const int* __restrict__ edst,
                       const float* __restrict__ ew) {
    int i = blockIdx.x * blockDim.x + threadIdx.x;
    if (i < NE) {
        int d = __ldcs(&edst[i]);
        int p = atomicAdd(&g_cursor[d], 1);
        g_edge[p] = make_int2(__ldcs(&esrc[i]), __float_as_int(__ldcs(&ew[i])));
    }
}

// ---------------- SpMM: g_sup = 0.9*Adj@hin + 0.1*h0, warp-per-row, 4-way MLP ----
__global__ void k_spmm(const float* __restrict__ hin) {
    int gw = (blockIdx.x * blockDim.x + threadIdx.x) >> 5;
    int lane = threadIdx.x & 31;
    if (gw >= NN) return;
    int s = g_rowptr[gw], e = g_rowptr[gw + 1];
    const float4* h4 = (const float4*)hin;
    float4 a0 = make_float4(0.f, 0.f, 0.f, 0.f);
    float4 a1 = make_float4(0.f, 0.f, 0.f, 0.f);
    int i = s;
    for (; i + 4 <= e; i += 4) {
        int2 e0 = __ldcs(&g_edge[i]);
        int2 e1 = __ldcs(&g_edge[i + 1]);
        int2 e2 = __ldcs(&g_edge[i + 2]);
        int2 e3 = __ldcs(&g_edge[i + 3]);
        float4 v0 = h4[e0.x * 32 + lane];
        float4 v1 = h4[e1.x * 32 + lane];
        float4 v2 = h4[e2.x * 32 + lane];
        float4 v3 = h4[e3.x * 32 + lane];
        float w0 = __int_as_float(e0.y), w1 = __int_as_float(e1.y);
        float w2 = __int_as_float(e2.y), w3 = __int_as_float(e3.y);
        a0.x += w0 * v0.x; a0.y += w0 * v0.y; a0.z += w0 * v0.z; a0.w += w0 * v0.w;
        a1.x += w1 * v1.x; a1.y += w1 * v1.y; a1.z += w1 * v1.z; a1.w += w1 * v1.w;
        a0.x += w2 * v2.x; a0.y += w2 * v2.y; a0.z += w2 * v2.z; a0.w += w2 * v2.w;
        a1.x += w3 * v3.x; a1.y += w3 * v3.y; a1.z += w3 * v3.z; a1.w += w3 * v3.w;
    }
    for (; i < e; i++) {
        int2 e0 = __ldcs(&g_edge[i]);
        float w = __int_as_float(e0.y);
        float4 v = h4[e0.x * 32 + lane];
        a0.x += w * v.x; a0.y += w * v.y; a0.z += w * v.z; a0.w += w * v.w;
    }
    a0.x += a1.x; a0.y += a1.y; a0.z += a1.z; a0.w += a1.w;
    const float4* h04 = (const float4*)g_h0;
    float4 z = __ldcs(&h04[gw * 32 + lane]);
    float4 r;
    r.x = 0.9f * a0.x + 0.1f * z.x;
    r.y = 0.9f * a0.y + 0.1f * z.y;
    r.z = 0.9f * a0.z + 0.1f * z.z;
    r.w = 0.9f * a0.w + 0.1f * z.w;
    __stcs(&((float4*)g_sup)[gw * 32 + lane], r);
}

// ---------------- GEMM: out = relu(S@(c0*W + c1*I) + hprev + bias) ----------------
// Broadcast-free f32x2: S stored transposed (ST[k][row]); row-pair packing.
// 8 warps x 8 rows; lane owns 4 cols. acc[p][c] = (out[2p][c], out[2p+1][c]).
__global__ void __launch_bounds__(256, 2) k_gemm(
    const float* __restrict__ A, const float* __restrict__ W,
    const float* __restrict__ hprev, const float* __restrict__ bias,
    float* __restrict__ out, float c0, float c1)
{
    extern __shared__ float sh[];
    float* Wsh = sh;                 // [128][128] = 64KB, holds c0*W + c1*I
    float* ST  = sh + DD * DD;       // [128][STP] transposed S tile
    int t = threadIdx.x;
    int warp = t >> 5, lane = t & 31;
    int base = blockIdx.x * 64;

    // Wsh = c0*W + c1*I
    const float4* W4 = (const float4*)W;
    float4* Wsh4 = (float4*)Wsh;
    #pragma unroll
    for (int i = 0; i < 16; i++) {
        int f = t + i * 256;
        int k = f >> 5, n0 = (f & 31) * 4;
        float4 w = W4[f];
        w.x *= c0; w.y *= c0; w.z *= c0; w.w *= c0;
        if (k - n0 >= 0 && k - n0 < 4) {
            if (k == n0)     w.x += c1;
            if (k == n0 + 1) w.y += c1;
            if (k == n0 + 2) w.z += c1;
            if (k == n0 + 3) w.w += c1;
        }
        Wsh4[f] = w;
    }

    // load A tile transposed: ST[k][row]
    const float4* A4 = (const float4*)A;
    #pragma unroll
    for (int i = 0; i < 8; i++) {
        int f = t + i * 256;              // float4 index, 0..2047
        int row = f >> 5, l = f & 31;
        int grow = base + row;
        float4 s = (grow < NN) ? A4[base * 32 + f] : make_float4(0.f, 0.f, 0.f, 0.f);
        ST[(4 * l + 0) * STP + row] = s.x;
        ST[(4 * l + 1) * STP + row] = s.y;
        ST[(4 * l + 2) * STP + row] = s.z;
        ST[(4 * l + 3) * STP + row] = s.w;
    }
    __syncthreads();

    int srow = warp * 8;
    uint64_t acc[4][4];
    #pragma unroll
    for (int p = 0; p < 4; p++)
        #pragma unroll
        for (int c = 0; c < 4; c++) acc[p][c] = 0ull;

    #pragma unroll 4
    for (int k = 0; k < DD; k++) {
        float4 w = Wsh4[k * 32 + lane];
        uint64_t b0 = bcast2(w.x), b1 = bcast2(w.y), b2 = bcast2(w.z), b3 = bcast2(w.w);
        const float* strow = &ST[k * STP + srow];
        #pragma unroll
        for (int p = 0; p < 4; p++) {
            uint64_t sp = *(const uint64_t*)(strow + 2 * p);   // (s_row2p, s_row2p+1)
            acc[p][0] = fma2(sp, b0, acc[p][0]);
            acc[p][1] = fma2(sp, b1, acc[p][1]);
            acc[p][2] = fma2(sp, b2, acc[p][2]);
            acc[p][3] = fma2(sp, b3, acc[p][3]);
        }
    }

    const float4* hp4 = (const float4*)hprev;
    const float4* b4 = (const float4*)bias;
    float4 bv = bias ? b4[lane] : make_float4(0.f, 0.f, 0.f, 0.f);
    #pragma unroll
    for (int p = 0; p < 4; p++) {
        float2 v0 = unpack2(acc[p][0]);
        float2 v1 = unpack2(acc[p][1]);
        float2 v2 = unpack2(acc[p][2]);
        float2 v3 = unpack2(acc[p][3]);
        #pragma unroll
        for (int h = 0; h < 2; h++) {
            int row = base + srow + 2 * p + h;
            if (row < NN) {
                float4 o;
                o.x = (h ? v0.y : v0.x) + bv.x;
                o.y = (h ? v1.y : v1.x) + bv.y;
                o.z = (h ? v2.y : v2.x) + bv.z;
                o.w = (h ? v3.y : v3.x) + bv.w;
                if (hprev) {
                    float4 hv = hp4[row * 32 + lane];
                    o.x += hv.x; o.y += hv.y; o.z += hv.z; o.w += hv.w;
                }
                o.x = fmaxf(o.x, 0.f); o.y = fmaxf(o.y, 0.f);
                o.z = fmaxf(o.z, 0.f); o.w = fmaxf(o.w, 0.f);
                ((float4*)out)[row * 32 + lane] = o;
            }
        }
    }
}

// ---------------- output head: logits = h@w_out + b_out -> log_softmax ----------------
__global__ void k_out(const float* __restrict__ hin, const float* __restrict__ wout,
                      const float* __restrict__ bout, float* __restrict__ out)
{
    __shared__ float Wsh[DD * CC];   // 32KB
    __shared__ float Hsh[8][DD];     // 4KB
    int t = threadIdx.x;

    float4* Wsh4 = (float4*)Wsh;
    const float4* w4 = (const float4*)wout;
    #pragma unroll
    for (int i = 0; i < 8; i++) Wsh4[t + i * 256] = w4[t + i * 256];
    __syncthreads();

    int warp = t >> 5, lane = t & 31;
    int row = blockIdx.x * 8 + warp;
    if (row >= NN) return;

    ((float4*)Hsh[warp])[lane] = ((const float4*)hin)[row * 32 + lane];
    __syncwarp();

    uint64_t accp = *(const uint64_t*)&bout[2 * lane];
    const uint64_t* Wshp = (const uint64_t*)Wsh;
    #pragma unroll 4
    for (int k = 0; k < DD; k++) {
        float hv = Hsh[warp][k];
        accp = fma2(bcast2(hv), Wshp[k * 32 + lane], accp);
    }
    float2 a = unpack2(accp);
    float a0 = a.x, a1 = a.y;

    float m = fmaxf(a0, a1);
    #pragma unroll
    for (int off = 16; off; off >>= 1) m = fmaxf(m, __shfl_xor_sync(0xffffffffu, m, off));
    float se = expf(a0 - m) + expf(a1 - m);
    #pragma unroll
    for (int off = 16; off; off >>= 1) se += __shfl_xor_sync(0xffffffffu, se, off);
    float lse = m + logf(se);

    out[row * 64 + 2 * lane]     = a0 - lse;
    out[row * 64 + 2 * lane + 1] = a1 - lse;
}

// ---------------- launch ----------------
extern "C" void kernel_launch(void* const* d_in, const int* in_sizes, int n_in,
                              void* d_out, int out_size)
{
    const float* x     = (const float*)d_in[0];
    const int*   esrc  = (const int*)  d_in[1];
    const int*   edst  = (const int*)  d_in[2];
    const float* ew    = (const float*)d_in[3];
    const float* w_in  = (const float*)d_in[4];
    const float* b_in  = (const float*)d_in[5];
    const float* gcn_w = (const float*)d_in[6];
    const float* w_out = (const float*)d_in[7];
    const float* b_out = (const float*)d_in[8];
    float* out = (float*)d_out;

    const int GEMM_SMEM = (DD * DD + DD * STP) * (int)sizeof(float); // 101376
    cudaFuncSetAttribute(k_gemm, cudaFuncAttributeMaxDynamicSharedMemorySize, GEMM_SMEM);

    void *ph0v, *phAv, *phBv, *psupv;
    cudaGetSymbolAddress(&ph0v, g_h0);
    cudaGetSymbolAddress(&phAv, g_hA);
    cudaGetSymbolAddress(&phBv, g_hB);
    cudaGetSymbolAddress(&psupv, g_sup);
    float* ph0 = (float*)ph0v;
    float* phA = (float*)phAv;
    float* phB = (float*)phBv;
    float* psup = (float*)psupv;

    const int NB = (NN + 1 + 1023) / 1024; // 98

    // CSR build
    k_zero_rowptr<<<(NN + 1 + 255) / 256, 256>>>();
    k_hist<<<(NE + 255) / 256, 256>>>(edst);
    k_scan1<<<NB, 1024>>>();
    k_scan2<<<1, 128>>>(NB);
    k_scan3<<<NB, 1024>>>();
    k_fill<<<(NE + 255) / 256, 256>>>(esrc, edst, ew);

    const int GB = (NN + 63) / 64;   // 1563 GEMM blocks
    const int SB = NN / 8;           // 12500 warp-per-row blocks

    // h0 = relu(x @ w_in + b_in)
    k_gemm<<<GB, 256, GEMM_SMEM>>>(x, w_in, nullptr, b_in, ph0, 1.0f, 0.0f);

    float theta[NL];
    for (int l = 0; l < NL; l++) theta[l] = logf(0.5f / (float)(l + 2) + 1.0f);

    for (int l = 0; l < NL; l++) {
        float* hin  = (l == 0) ? ph0 : ((l & 1) ? phA : phB);
        float* hout = (l & 1) ? phB : phA;
        k_spmm<<<SB, 256>>>(hin);                       // g_sup = 0.9*Adj@hin + 0.1*h0
        k_gemm<<<GB, 256, GEMM_SMEM>>>(psup, gcn_w + l * DD * DD, hin, nullptr,
                                       hout, theta[l], 1.0f - theta[l]);
    }

    // final h in g_hB (l=3 -> hout=phB)
    k_out<<<SB, 256>>>(phB, w_out, b_out, out);
}

// round 15
// speedup vs baseline: 1.1809x; 1.0428x over previous
#include <cuda_runtime.h>
#include <cuda_bf16.h>
#include <math.h>
#include <stdint.h>

#define NN 100000
#define NE 1600000
#define DD 128
#define CC 64
#define NL 4

// ---------------- scratch (device globals: allocation-free) ----------------
__device__ float g_h0[NN * DD];
__device__ float g_hA[NN * DD];
__device__ float g_hB[NN * DD];
__device__ float g_sup[NN * DD];
__device__ int   g_rowptr[NN + 1];
__device__ int   g_cursor[NN];
__device__ int2  g_edge[NE];        // packed (col, val-as-int)
__device__ int   g_bsum[128];

// ---------------- warp-MMA helpers (sm_80-class PTX) ----------------
__device__ __forceinline__ uint32_t smem_u32(const void* p) {
    uint32_t a;
    asm("{ .reg .u64 t; cvta.to.shared.u64 t, %1; cvt.u32.u64 %0, t; }" : "=r"(a) : "l"(p));
    return a;
}
__device__ __forceinline__ void ldm_x4(uint32_t& a0, uint32_t& a1, uint32_t& a2, uint32_t& a3,
                                       uint32_t addr) {
    asm volatile("ldmatrix.sync.aligned.m8n8.x4.shared.b16 {%0,%1,%2,%3}, [%4];"
                 : "=r"(a0), "=r"(a1), "=r"(a2), "=r"(a3) : "r"(addr));
}
__device__ __forceinline__ void ldm_x2t(uint32_t& b0, uint32_t& b1, uint32_t addr) {
    asm volatile("ldmatrix.sync.aligned.m8n8.x2.trans.shared.b16 {%0,%1}, [%2];"
                 : "=r"(b0), "=r"(b1) : "r"(addr));
}
__device__ __forceinline__ void mma_bf16(float* c, uint32_t a0, uint32_t a1, uint32_t a2,
                                         uint32_t a3, uint32_t b0, uint32_t b1) {
    asm volatile(
        "mma.sync.aligned.m16n8k16.row.col.f32.bf16.bf16.f32 "
        "{%0,%1,%2,%3}, {%4,%5,%6,%7}, {%8,%9}, {%0,%1,%2,%3};"
        : "+f"(c[0]), "+f"(c[1]), "+f"(c[2]), "+f"(c[3])
        : "r"(a0), "r"(a1), "r"(a2), "r"(a3), "r"(b0), "r"(b1));
}
__device__ __forceinline__ void split_bf16(float v, __nv_bfloat16& h, __nv_bfloat16& l) {
    h = __float2bfloat16(v);
    l = __float2bfloat16(v - __bfloat162float(h));
}
__device__ __forceinline__ uint64_t bcast2(float v) {
    uint64_t r;
    asm("mov.b64 %0, {%1, %1};" : "=l"(r) : "f"(v));
    return r;
}
__device__ __forceinline__ uint64_t fma2(uint64_t a, uint64_t b, uint64_t c) {
    uint64_t d;
    asm("fma.rn.f32x2 %0, %1, %2, %3;" : "=l"(d) : "l"(a), "l"(b), "l"(c));
    return d;
}
__device__ __forceinline__ float2 unpack2(uint64_t v) {
    float2 f;
    asm("mov.b64 {%0, %1}, %2;" : "=f"(f.x), "=f"(f.y) : "l"(v));
    return f;
}

// ---------------- CSR build (g_rowptr zeroed by k_out of previous call) ------
__global__ void k_hist(const int* __restrict__ edst) {
    int i = blockIdx.x * blockDim.x + threadIdx.x;
    if (i < NE) atomicAdd(&g_rowptr[__ldcs(&edst[i]) + 1], 1);
}
__global__ void k_scan1() {
    __shared__ int sh[2][1024];
    int t = threadIdx.x;
    int i = blockIdx.x * 1024 + t;
    int v = (i <= NN) ? g_rowptr[i] : 0;
    sh[0][t] = v;
    __syncthreads();
    int p = 0;
    #pragma unroll
    for (int off = 1; off < 1024; off <<= 1) {
        int q = p ^ 1;
        int add = (t >= off) ? sh[p][t - off] : 0;
        sh[q][t] = sh[p][t] + add;
        __syncthreads();
        p = q;
    }
    if (i <= NN) g_rowptr[i] = sh[p][t];
    if (t == 1023) g_bsum[blockIdx.x] = sh[p][1023];
}
__global__ void k_scan2(int nb) {
    __shared__ int sh[128];
    int t = threadIdx.x;
    if (t < nb) sh[t] = g_bsum[t];
    __syncthreads();
    if (t == 0) {
        int s = 0;
        for (int b = 0; b < nb; b++) { s += sh[b]; sh[b] = s; }
    }
    __syncthreads();
    if (t < nb) g_bsum[t] = sh[t];
}
__global__ void k_scan3() {
    int t = threadIdx.x;
    int i = blockIdx.x * 1024 + t;
    if (i <= NN) {
        int v = g_rowptr[i];
        if (blockIdx.x > 0) v += g_bsum[blockIdx.x - 1];
        g_rowptr[i] = v;
        if (i < NN) g_cursor[i] = v;
    }
}
__global__ void k_fill(const int* __restrict__ esrc, const int* __restrict__ edst,
                       const float* __restrict__ ew) {
    int i = blockIdx.x * blockDim.x + threadIdx.x;
    if (i < NE) {
        int d = __ldcs(&edst[i]);
        int p = atomicAdd(&g_cursor[d], 1);
        g_edge[p] = make_int2(__ldcs(&esrc[i]), __float_as_int(__ldcs(&ew[i])));
    }
}

// ---------------- SpMM: g_sup = 0.9*Adj@hin + 0.1*h0, warp-per-row ----------
__global__ void k_spmm(const float* __restrict__ hin) {
    int gw = (blockIdx.x * blockDim.x + threadIdx.x) >> 5;
    int lane = threadIdx.x & 31;
    if (gw >= NN) return;
    int s = g_rowptr[gw], e = g_rowptr[gw + 1];
    const float4* h4 = (const float4*)hin;
    float4 a0 = make_float4(0.f, 0.f, 0.f, 0.f);
    float4 a1 = make_float4(0.f, 0.f, 0.f, 0.f);
    int i = s;
    for (; i + 4 <= e; i += 4) {
        int2 e0 = __ldcs(&g_edge[i]);
        int2 e1 = __ldcs(&g_edge[i + 1]);
        int2 e2 = __ldcs(&g_edge[i + 2]);
        int2 e3 = __ldcs(&g_edge[i + 3]);
        float4 v0 = h4[e0.x * 32 + lane];
        float4 v1 = h4[e1.x * 32 + lane];
        float4 v2 = h4[e2.x * 32 + lane];
        float4 v3 = h4[e3.x * 32 + lane];
        float w0 = __int_as_float(e0.y), w1 = __int_as_float(e1.y);
        float w2 = __int_as_float(e2.y), w3 = __int_as_float(e3.y);
        a0.x += w0 * v0.x; a0.y += w0 * v0.y; a0.z += w0 * v0.z; a0.w += w0 * v0.w;
        a1.x += w1 * v1.x; a1.y += w1 * v1.y; a1.z += w1 * v1.z; a1.w += w1 * v1.w;
        a0.x += w2 * v2.x; a0.y += w2 * v2.y; a0.z += w2 * v2.z; a0.w += w2 * v2.w;
        a1.x += w3 * v3.x; a1.y += w3 * v3.y; a1.z += w3 * v3.z; a1.w += w3 * v3.w;
    }
    for (; i < e; i++) {
        int2 e0 = __ldcs(&g_edge[i]);
        float w = __int_as_float(e0.y);
        float4 v = h4[e0.x * 32 + lane];
        a0.x += w * v.x; a0.y += w * v.y; a0.z += w * v.z; a0.w += w * v.w;
    }
    a0.x += a1.x; a0.y += a1.y; a0.z += a1.z; a0.w += a1.w;
    const float4* h04 = (const float4*)g_h0;
    float4 z = __ldg(&h04[gw * 32 + lane]);
    float4 r;
    r.x = 0.9f * a0.x + 0.1f * z.x;
    r.y = 0.9f * a0.y + 0.1f * z.y;
    r.z = 0.9f * a0.z + 0.1f * z.z;
    r.w = 0.9f * a0.w + 0.1f * z.w;
    ((float4*)g_sup)[gw * 32 + lane] = r;
}

// ---------------- HMMA GEMM: out = relu(c0*(A@W) + c1*A + hprev + bias) -------
// bf16x3 split-precision mma.sync m16n8k16. Block tile 64(M)x128(N), K=128.
// 8 warps: mw = w&1 (M group of 32), nw = w>>1 (N group of 32). Warp tile 32x32.
// SMEM: Ahi|Alo 64x136 bf16 (17408B each); Bhi|Blo 128x136 bf16 (34816B each).
#define PADK 136
#define OFF_AHI 0
#define OFF_ALO 17408
#define OFF_BHI 34816
#define OFF_BLO 69632
#define MMA_SMEM 104448

__global__ void __launch_bounds__(256, 2) k_gemm_mma(
    const float* __restrict__ A, const float* __restrict__ W,
    const float* __restrict__ hprev, const float* __restrict__ bias,
    float* __restrict__ out, float c0, float c1)
{
    extern __shared__ char sm[];
    uint32_t sb = smem_u32(sm);
    int t = threadIdx.x, lane = t & 31, warp = t >> 5;
    int mw = warp & 1, nw = warp >> 1;
    int base = blockIdx.x * 64;

    __nv_bfloat162* Ahi = (__nv_bfloat162*)(sm + OFF_AHI);
    __nv_bfloat162* Alo = (__nv_bfloat162*)(sm + OFF_ALO);
    __nv_bfloat162* Bhi = (__nv_bfloat162*)(sm + OFF_BHI);
    __nv_bfloat162* Blo = (__nv_bfloat162*)(sm + OFF_BLO);

    // A tile: [m][k], 64 rows of 136 bf16 (bf16x2 units: row*68 + k/2)
    const float4* A4 = (const float4*)(A + (size_t)base * DD);
    #pragma unroll
    for (int i = 0; i < 8; i++) {
        int f = t + i * 256;               // 0..2047
        int row = f >> 5, c4 = f & 31, grow = base + row;
        float4 s = make_float4(0.f, 0.f, 0.f, 0.f);
        if (grow < NN) s = A4[f];
        __nv_bfloat16 hx, lx, hy, ly, hz, lz, hw, lw;
        split_bf16(s.x, hx, lx); split_bf16(s.y, hy, ly);
        split_bf16(s.z, hz, lz); split_bf16(s.w, hw, lw);
        int idx = row * 68 + c4 * 2;
        Ahi[idx]     = __nv_bfloat162(hx, hy);
        Ahi[idx + 1] = __nv_bfloat162(hz, hw);
        Alo[idx]     = __nv_bfloat162(lx, ly);
        Alo[idx + 1] = __nv_bfloat162(lz, lw);
    }
    // B tile: W[k][n] natural layout, 128 rows of 136 bf16
    const float4* W4 = (const float4*)W;
    #pragma unroll
    for (int i = 0; i < 16; i++) {
        int f = t + i * 256;               // 0..4095
        int k = f >> 5, c4 = f & 31;
        float4 s = W4[f];
        __nv_bfloat16 hx, lx, hy, ly, hz, lz, hw, lw;
        split_bf16(s.x, hx, lx); split_bf16(s.y, hy, ly);
        split_bf16(s.z, hz, lz); split_bf16(s.w, hw, lw);
        int idx = k * 68 + c4 * 2;
        Bhi[idx]     = __nv_bfloat162(hx, hy);
        Bhi[idx + 1] = __nv_bfloat162(hz, hw);
        Blo[idx]     = __nv_bfloat162(lx, ly);
        Blo[idx + 1] = __nv_bfloat162(lz, lw);
    }
    __syncthreads();

    float acc[2][4][4];
    #pragma unroll
    for (int mt = 0; mt < 2; mt++)
        #pragma unroll
        for (int nt = 0; nt < 4; nt++)
            #pragma unroll
            for (int j = 0; j < 4; j++) acc[mt][nt][j] = 0.f;

    // A x4: lanes 0-15 -> row (m0+l), k0 ; lanes 16-31 -> row (m0+l-16), k0+8
    int arow = mw * 32 + (lane & 15);
    int akoff = (lane >> 4) * 8;
    // B x2.trans: lanes 0-15 -> row (k0+l), n0
    int bk = lane & 15;

    const uint32_t offA[3] = { OFF_AHI, OFF_AHI, OFF_ALO };
    const uint32_t offB[3] = { OFF_BHI, OFF_BLO, OFF_BHI };

    #pragma unroll
    for (int p = 0; p < 3; p++) {
        uint32_t aB = sb + offA[p];
        uint32_t bB = sb + offB[p];
        #pragma unroll
        for (int ks = 0; ks < 8; ks++) {
            int k0 = ks * 16;
            uint32_t af[2][4];
            #pragma unroll
            for (int mt = 0; mt < 2; mt++) {
                uint32_t addr = aB + (uint32_t)(((arow + mt * 16) * PADK + k0 + akoff) * 2);
                ldm_x4(af[mt][0], af[mt][1], af[mt][2], af[mt][3], addr);
            }
            uint32_t bf[4][2];
            #pragma unroll
            for (int nt = 0; nt < 4; nt++) {
                uint32_t addr = bB + (uint32_t)(((k0 + bk) * PADK + nw * 32 + nt * 8) * 2);
                ldm_x2t(bf[nt][0], bf[nt][1], addr);
            }
            #pragma unroll
            for (int mt = 0; mt < 2; mt++)
                #pragma unroll
                for (int nt = 0; nt < 4; nt++)
                    mma_bf16(acc[mt][nt], af[mt][0], af[mt][1], af[mt][2], af[mt][3],
                             bf[nt][0], bf[nt][1]);
        }
    }

    // epilogue: c0,c1 @ (r + l/4, c + 2*(l%4)), c2,c3 @ r+8
    int rbase = base + mw * 32 + (lane >> 2);
    int cbase = nw * 32 + 2 * (lane & 3);
    #pragma unroll
    for (int mt = 0; mt < 2; mt++) {
        #pragma unroll
        for (int half = 0; half < 2; half++) {
            int grow = rbase + mt * 16 + half * 8;
            if (grow >= NN) continue;
            const float* arow_p = A + (size_t)grow * DD;
            const float* hrow_p = hprev ? hprev + (size_t)grow * DD : (const float*)0;
            float* orow_p = out + (size_t)grow * DD;
            #pragma unroll
            for (int nt = 0; nt < 4; nt++) {
                int gc = cbase + nt * 8;
                float2 av = *(const float2*)(arow_p + gc);
                float vx = acc[mt][nt][half * 2 + 0];
                float vy = acc[mt][nt][half * 2 + 1];
                float ox = c0 * vx + c1 * av.x;
                float oy = c0 * vy + c1 * av.y;
                if (hrow_p) {
                    float2 hv = *(const float2*)(hrow_p + gc);
                    ox += hv.x; oy += hv.y;
                }
                if (bias) {
                    float2 bv = *(const float2*)(bias + gc);
                    ox += bv.x; oy += bv.y;
                }
                *(float2*)(orow_p + gc) = make_float2(fmaxf(ox, 0.f), fmaxf(oy, 0.f));
            }
        }
    }
}

// ---------------- output head + g_rowptr cleanup for next call ----------------
__global__ void k_out(const float* __restrict__ hin, const float* __restrict__ wout,
                      const float* __restrict__ bout, float* __restrict__ out)
{
    __shared__ float Wsh[DD * CC];   // 32KB
    __shared__ float Hsh[8][DD];     // 4KB
    int t = threadIdx.x;

    // restore invariant: g_rowptr == 0 at entry of next kernel_launch call
    int gi = blockIdx.x * blockDim.x + t;
    if (gi <= NN) g_rowptr[gi] = 0;

    float4* Wsh4 = (float4*)Wsh;
    const float4* w4 = (const float4*)wout;
    #pragma unroll
    for (int i = 0; i < 8; i++) Wsh4[t + i * 256] = w4[t + i * 256];
    __syncthreads();

    int warp = t >> 5, lane = t & 31;
    int row = blockIdx.x * 8 + warp;
    if (row >= NN) return;

    ((float4*)Hsh[warp])[lane] = ((const float4*)hin)[row * 32 + lane];
    __syncwarp();

    uint64_t accp = *(const uint64_t*)&bout[2 * lane];
    const uint64_t* Wshp = (const uint64_t*)Wsh;
    #pragma unroll 4
    for (int k = 0; k < DD; k++) {
        float hv = Hsh[warp][k];
        accp = fma2(bcast2(hv), Wshp[k * 32 + lane], accp);
    }
    float2 a = unpack2(accp);
    float a0 = a.x, a1 = a.y;

    float m = fmaxf(a0, a1);
    #pragma unroll
    for (int off = 16; off; off >>= 1) m = fmaxf(m, __shfl_xor_sync(0xffffffffu, m, off));
    float se = expf(a0 - m) + expf(a1 - m);
    #pragma unroll
    for (int off = 16; off; off >>= 1) se += __shfl_xor_sync(0xffffffffu, se, off);
    float lse = m + logf(se);

    out[row * 64 + 2 * lane]     = a0 - lse;
    out[row * 64 + 2 * lane + 1] = a1 - lse;
}

// ---------------- launch ----------------
extern "C" void kernel_launch(void* const* d_in, const int* in_sizes, int n_in,
                              void* d_out, int out_size)
{
    const float* x     = (const float*)d_in[0];
    const int*   esrc  = (const int*)  d_in[1];
    const int*   edst  = (const int*)  d_in[2];
    const float* ew    = (const float*)d_in[3];
    const float* w_in  = (const float*)d_in[4];
    const float* b_in  = (const float*)d_in[5];
    const float* gcn_w = (const float*)d_in[6];
    const float* w_out = (const float*)d_in[7];
    const float* b_out = (const float*)d_in[8];
    float* out = (float*)d_out;

    cudaFuncSetAttribute(k_gemm_mma, cudaFuncAttributeMaxDynamicSharedMemorySize, MMA_SMEM);

    void *ph0v, *phAv, *phBv, *psupv;
    cudaGetSymbolAddress(&ph0v, g_h0);
    cudaGetSymbolAddress(&phAv, g_hA);
    cudaGetSymbolAddress(&phBv, g_hB);
    cudaGetSymbolAddress(&psupv, g_sup);
    float* ph0 = (float*)ph0v;
    float* phA = (float*)phAv;
    float* phB = (float*)phBv;
    float* psup = (float*)psupv;

    const int NB = (NN + 1 + 1023) / 1024; // 98

    // CSR build (g_rowptr zeroed by previous call's k_out; BSS-zero on first call)
    k_hist<<<(NE + 255) / 256, 256>>>(edst);
    k_scan1<<<NB, 1024>>>();
    k_scan2<<<1, 128>>>(NB);
    k_scan3<<<NB, 1024>>>();
    k_fill<<<(NE + 255) / 256, 256>>>(esrc, edst, ew);

    const int GB = (NN + 63) / 64;   // 1563 MMA blocks (64 rows each)
    const int SB = NN / 8;           // 12500 warp-per-row blocks

    // h0 = relu(x @ w_in + b_in)
    k_gemm_mma<<<GB, 256, MMA_SMEM>>>(x, w_in, nullptr, b_in, ph0, 1.0f, 0.0f);

    float theta[NL];
    for (int l = 0; l < NL; l++) theta[l] = logf(0.5f / (float)(l + 2) + 1.0f);

    for (int l = 0; l < NL; l++) {
        float* hin  = (l == 0) ? ph0 : ((l & 1) ? phA : phB);
        float* hout = (l & 1) ? phB : phA;
        k_spmm<<<SB, 256>>>(hin);  // g_sup = 0.9*Adj@hin + 0.1*h0
        // hout = relu(theta*(sup@W) + (1-theta)*sup + hin)
        k_gemm_mma<<<GB, 256, MMA_SMEM>>>(psup, gcn_w + l * DD * DD, hin, nullptr,
                                          hout, theta[l], 1.0f - theta[l]);
    }

    // final h in g_hB (l=3 -> hout=phB)
    k_out<<<SB, 256>>>(phB, w_out, b_out, out);
}

// round 17
// speedup vs baseline: 1.1962x; 1.0130x over previous
#include <cuda_runtime.h>
#include <cuda_bf16.h>
#include <math.h>
#include <stdint.h>

#define NN 100000
#define NE 1600000
#define DD 128
#define CC 64
#define NL 4

// ---------------- scratch (device globals: allocation-free) ----------------
__device__ float g_h0[NN * DD];
__device__ float g_hA[NN * DD];
__device__ float g_hB[NN * DD];
__device__ __nv_bfloat16 g_AH[NN * DD];      // A (sup or x) split hi
__device__ __nv_bfloat16 g_AL[NN * DD];      // A split lo
__device__ __nv_bfloat16 g_WH[5 * DD * DD];  // weights split hi (w_in + 4 layers)
__device__ __nv_bfloat16 g_WL[5 * DD * DD];
__device__ int   g_rowptr[NN + 1];
__device__ int   g_cursor[NN];
__device__ int2  g_edge[NE];
__device__ int   g_bsum[128];

// ---------------- helpers ----------------
__device__ __forceinline__ uint32_t smem_u32(const void* p) {
    uint32_t a;
    asm("{ .reg .u64 t; cvta.to.shared.u64 t, %1; cvt.u32.u64 %0, t; }" : "=r"(a) : "l"(p));
    return a;
}
__device__ __forceinline__ void ldm_x4(uint32_t& a0, uint32_t& a1, uint32_t& a2, uint32_t& a3,
                                       uint32_t addr) {
    asm volatile("ldmatrix.sync.aligned.m8n8.x4.shared.b16 {%0,%1,%2,%3}, [%4];"
                 : "=r"(a0), "=r"(a1), "=r"(a2), "=r"(a3) : "r"(addr));
}
__device__ __forceinline__ void ldm_x2t(uint32_t& b0, uint32_t& b1, uint32_t addr) {
    asm volatile("ldmatrix.sync.aligned.m8n8.x2.trans.shared.b16 {%0,%1}, [%2];"
                 : "=r"(b0), "=r"(b1) : "r"(addr));
}
__device__ __forceinline__ void mma_bf16(float* c, uint32_t a0, uint32_t a1, uint32_t a2,
                                         uint32_t a3, uint32_t b0, uint32_t b1) {
    asm volatile(
        "mma.sync.aligned.m16n8k16.row.col.f32.bf16.bf16.f32 "
        "{%0,%1,%2,%3}, {%4,%5,%6,%7}, {%8,%9}, {%0,%1,%2,%3};"
        : "+f"(c[0]), "+f"(c[1]), "+f"(c[2]), "+f"(c[3])
        : "r"(a0), "r"(a1), "r"(a2), "r"(a3), "r"(b0), "r"(b1));
}
__device__ __forceinline__ void split_bf16(float v, __nv_bfloat16& h, __nv_bfloat16& l) {
    h = __float2bfloat16(v);
    l = __float2bfloat16(v - __bfloat162float(h));
}
__device__ __forceinline__ uint64_t bcast2(float v) {
    uint64_t r;
    asm("mov.b64 %0, {%1, %1};" : "=l"(r) : "f"(v));
    return r;
}
__device__ __forceinline__ uint64_t fma2(uint64_t a, uint64_t b, uint64_t c) {
    uint64_t d;
    asm("fma.rn.f32x2 %0, %1, %2, %3;" : "=l"(d) : "l"(a), "l"(b), "l"(c));
    return d;
}
__device__ __forceinline__ float2 unpack2(uint64_t v) {
    float2 f;
    asm("mov.b64 {%0, %1}, %2;" : "=f"(f.x), "=f"(f.y) : "l"(v));
    return f;
}

// ---------------- pre-split kernels ----------------
__global__ void k_wsplit(const float* __restrict__ w_in, const float* __restrict__ gcn_w) {
    int i = blockIdx.x * blockDim.x + threadIdx.x;   // 0 .. 5*16384
    if (i < 5 * DD * DD) {
        float v = (i < DD * DD) ? w_in[i] : gcn_w[i - DD * DD];
        __nv_bfloat16 h, l;
        split_bf16(v, h, l);
        g_WH[i] = h;
        g_WL[i] = l;
    }
}
__global__ void k_xsplit(const float* __restrict__ x) {
    int i = blockIdx.x * blockDim.x + threadIdx.x;   // bf162 index, 0 .. NN*64
    if (i < NN * (DD / 2)) {
        float2 v = ((const float2*)x)[i];
        __nv_bfloat16 hx, lx, hy, ly;
        split_bf16(v.x, hx, lx);
        split_bf16(v.y, hy, ly);
        ((__nv_bfloat162*)g_AH)[i] = __nv_bfloat162(hx, hy);
        ((__nv_bfloat162*)g_AL)[i] = __nv_bfloat162(lx, ly);
    }
}

// ---------------- CSR build (g_rowptr zeroed by k_out of previous call) ------
__global__ void k_hist(const int* __restrict__ edst) {
    int i = blockIdx.x * blockDim.x + threadIdx.x;
    if (i < NE) atomicAdd(&g_rowptr[__ldcs(&edst[i]) + 1], 1);
}
__global__ void k_scan1() {
    __shared__ int sh[2][1024];
    int t = threadIdx.x;
    int i = blockIdx.x * 1024 + t;
    int v = (i <= NN) ? g_rowptr[i] : 0;
    sh[0][t] = v;
    __syncthreads();
    int p = 0;
    #pragma unroll
    for (int off = 1; off < 1024; off <<= 1) {
        int q = p ^ 1;
        int add = (t >= off) ? sh[p][t - off] : 0;
        sh[q][t] = sh[p][t] + add;
        __syncthreads();
        p = q;
    }
    if (i <= NN) g_rowptr[i] = sh[p][t];
    if (t == 1023) g_bsum[blockIdx.x] = sh[p][1023];
}
__global__ void k_scan2(int nb) {
    __shared__ int sh[128];
    int t = threadIdx.x;
    if (t < nb) sh[t] = g_bsum[t];
    __syncthreads();
    if (t == 0) {
        int s = 0;
        for (int b = 0; b < nb; b++) { s += sh[b]; sh[b] = s; }
    }
    __syncthreads();
    if (t < nb) g_bsum[t] = sh[t];
}
__global__ void k_scan3() {
    int t = threadIdx.x;
    int i = blockIdx.x * 1024 + t;
    if (i <= NN) {
        int v = g_rowptr[i];
        if (blockIdx.x > 0) v += g_bsum[blockIdx.x - 1];
        g_rowptr[i] = v;
        if (i < NN) g_cursor[i] = v;
    }
}
__global__ void k_fill(const int* __restrict__ esrc, const int* __restrict__ edst,
                       const float* __restrict__ ew) {
    int i = blockIdx.x * blockDim.x + threadIdx.x;
    if (i < NE) {
        int d = __ldcs(&edst[i]);
        int p = atomicAdd(&g_cursor[d], 1);
        g_edge[p] = make_int2(__ldcs(&esrc[i]), __float_as_int(__ldcs(&ew[i])));
    }
}

// ---------------- SpMM: sup = 0.9*Adj@hin + 0.1*h0, output split to bf16 hi/lo ----
__global__ void k_spmm(const float* __restrict__ hin) {
    int gw = (blockIdx.x * blockDim.x + threadIdx.x) >> 5;
    int lane = threadIdx.x & 31;
    if (gw >= NN) return;
    int s = g_rowptr[gw], e = g_rowptr[gw + 1];
    const float4* h4 = (const float4*)hin;
    float4 a0 = make_float4(0.f, 0.f, 0.f, 0.f);
    float4 a1 = make_float4(0.f, 0.f, 0.f, 0.f);
    int i = s;
    for (; i + 4 <= e; i += 4) {
        int2 e0 = __ldcs(&g_edge[i]);
        int2 e1 = __ldcs(&g_edge[i + 1]);
        int2 e2 = __ldcs(&g_edge[i + 2]);
        int2 e3 = __ldcs(&g_edge[i + 3]);
        float4 v0 = h4[e0.x * 32 + lane];
        float4 v1 = h4[e1.x * 32 + lane];
        float4 v2 = h4[e2.x * 32 + lane];
        float4 v3 = h4[e3.x * 32 + lane];
        float w0 = __int_as_float(e0.y), w1 = __int_as_float(e1.y);
        float w2 = __int_as_float(e2.y), w3 = __int_as_float(e3.y);
        a0.x += w0 * v0.x; a0.y += w0 * v0.y; a0.z += w0 * v0.z; a0.w += w0 * v0.w;
        a1.x += w1 * v1.x; a1.y += w1 * v1.y; a1.z += w1 * v1.z; a1.w += w1 * v1.w;
        a0.x += w2 * v2.x; a0.y += w2 * v2.y; a0.z += w2 * v2.z; a0.w += w2 * v2.w;
        a1.x += w3 * v3.x; a1.y += w3 * v3.y; a1.z += w3 * v3.z; a1.w += w3 * v3.w;
    }
    for (; i < e; i++) {
        int2 e0 = __ldcs(&g_edge[i]);
        float w = __int_as_float(e0.y);
        float4 v = h4[e0.x * 32 + lane];
        a0.x += w * v.x; a0.y += w * v.y; a0.z += w * v.z; a0.w += w * v.w;
    }
    a0.x += a1.x; a0.y += a1.y; a0.z += a1.z; a0.w += a1.w;
    const float4* h04 = (const float4*)g_h0;
    float4 z = __ldcs(&h04[gw * 32 + lane]);
    float4 r;
    r.x = 0.9f * a0.x + 0.1f * z.x;
    r.y = 0.9f * a0.y + 0.1f * z.y;
    r.z = 0.9f * a0.z + 0.1f * z.z;
    r.w = 0.9f * a0.w + 0.1f * z.w;
    // split to hi/lo and store (coalesced 8B per array per lane)
    __nv_bfloat16 hx, lx, hy, ly, hz, lz, hw, lw;
    split_bf16(r.x, hx, lx); split_bf16(r.y, hy, ly);
    split_bf16(r.z, hz, lz); split_bf16(r.w, hw, lw);
    __nv_bfloat162 hh[2] = { __nv_bfloat162(hx, hy), __nv_bfloat162(hz, hw) };
    __nv_bfloat162 ll[2] = { __nv_bfloat162(lx, ly), __nv_bfloat162(lz, lw) };
    *(uint2*)&g_AH[gw * DD + lane * 4] = *(uint2*)hh;
    *(uint2*)&g_AL[gw * DD + lane * 4] = *(uint2*)ll;
}

// ---------------- HMMA GEMM: out = relu(c0*(A@W) + c1*A + hprev + bias) -------
// A/W pre-split to bf16 hi/lo in gmem; blocks do pure copies (no conversion).
// Block tile 64(M)x128(N), K=128. 8 warps, warp tile 32x32, 2 CTAs/SM.
#define PADK 136
#define OFF_AHI 0
#define OFF_ALO 17408
#define OFF_BHI 34816
#define OFF_BLO 69632
#define MMA_SMEM 104448

__global__ void __launch_bounds__(256, 2) k_gemm_mma(
    const __nv_bfloat16* __restrict__ AH, const __nv_bfloat16* __restrict__ AL,
    const __nv_bfloat16* __restrict__ WH, const __nv_bfloat16* __restrict__ WL,
    const float* __restrict__ hprev, const float* __restrict__ bias,
    float* __restrict__ out, float c0, float c1)
{
    extern __shared__ char sm[];
    uint32_t sb = smem_u32(sm);
    int t = threadIdx.x, lane = t & 31, warp = t >> 5;
    int mw = warp & 1, nw = warp >> 1;
    int base = blockIdx.x * 64;

    // A tiles: 64 rows x 128 bf16 (256B/row) -> padded 272B rows. 1024 uint4 each.
    {
        const uint4* srcH = (const uint4*)(AH + (size_t)base * DD);
        const uint4* srcL = (const uint4*)(AL + (size_t)base * DD);
        #pragma unroll
        for (int i = 0; i < 4; i++) {
            int f = t + i * 256;               // 0..1023
            int row = f >> 4, koff = (f & 15) * 8;
            int grow = base + row;
            uint4 vh = make_uint4(0u, 0u, 0u, 0u), vl = vh;
            if (grow < NN) { vh = srcH[f]; vl = srcL[f]; }
            *(uint4*)(sm + OFF_AHI + row * 272 + koff * 2) = vh;
            *(uint4*)(sm + OFF_ALO + row * 272 + koff * 2) = vl;
        }
    }
    // B tiles: 128 rows x 128 bf16 -> padded. 2048 uint4 each.
    {
        const uint4* srcH = (const uint4*)WH;
        const uint4* srcL = (const uint4*)WL;
        #pragma unroll
        for (int i = 0; i < 8; i++) {
            int f = t + i * 256;               // 0..2047
            int row = f >> 4, koff = (f & 15) * 8;
            *(uint4*)(sm + OFF_BHI + row * 272 + koff * 2) = srcH[f];
            *(uint4*)(sm + OFF_BLO + row * 272 + koff * 2) = srcL[f];
        }
    }
    __syncthreads();

    float acc[2][4][4];
    #pragma unroll
    for (int mt = 0; mt < 2; mt++)
        #pragma unroll
        for (int nt = 0; nt < 4; nt++)
            #pragma unroll
            for (int j = 0; j < 4; j++) acc[mt][nt][j] = 0.f;

    int arow = mw * 32 + (lane & 15);
    int akoff = (lane >> 4) * 8;
    int bk = lane & 15;

    const uint32_t offA[3] = { OFF_AHI, OFF_AHI, OFF_ALO };
    const uint32_t offB[3] = { OFF_BHI, OFF_BLO, OFF_BHI };

    #pragma unroll
    for (int p = 0; p < 3; p++) {
        uint32_t aB = sb + offA[p];
        uint32_t bB = sb + offB[p];
        #pragma unroll
        for (int ks = 0; ks < 8; ks++) {
            int k0 = ks * 16;
            uint32_t af[2][4];
            #pragma unroll
            for (int mt = 0; mt < 2; mt++) {
                uint32_t addr = aB + (uint32_t)(((arow + mt * 16) * PADK + k0 + akoff) * 2);
                ldm_x4(af[mt][0], af[mt][1], af[mt][2], af[mt][3], addr);
            }
            uint32_t bf[4][2];
            #pragma unroll
            for (int nt = 0; nt < 4; nt++) {
                uint32_t addr = bB + (uint32_t)(((k0 + bk) * PADK + nw * 32 + nt * 8) * 2);
                ldm_x2t(bf[nt][0], bf[nt][1], addr);
            }
            #pragma unroll
            for (int mt = 0; mt < 2; mt++)
                #pragma unroll
                for (int nt = 0; nt < 4; nt++)
                    mma_bf16(acc[mt][nt], af[mt][0], af[mt][1], af[mt][2], af[mt][3],
                             bf[nt][0], bf[nt][1]);
        }
    }

    // epilogue: sup reconstructed from smem hi+lo; c0,c1 @ (r+l/4, c+2*(l%4)), c2,c3 @ r+8
    int rloc = mw * 32 + (lane >> 2);
    int cbase = nw * 32 + 2 * (lane & 3);
    const __nv_bfloat162* AhiV = (const __nv_bfloat162*)(sm + OFF_AHI);
    const __nv_bfloat162* AloV = (const __nv_bfloat162*)(sm + OFF_ALO);
    #pragma unroll
    for (int mt = 0; mt < 2; mt++) {
        #pragma unroll
        for (int half = 0; half < 2; half++) {
            int lrow = rloc + mt * 16 + half * 8;
            int grow = base + lrow;
            if (grow >= NN) continue;
            const float* hrow_p = hprev ? hprev + (size_t)grow * DD : (const float*)0;
            float* orow_p = out + (size_t)grow * DD;
            #pragma unroll
            for (int nt = 0; nt < 4; nt++) {
                int gc = cbase + nt * 8;
                int sidx = lrow * (PADK / 2) + (gc >> 1);
                float2 ah = __bfloat1622float2(AhiV[sidx]);
                float2 al = __bfloat1622float2(AloV[sidx]);
                float supx = ah.x + al.x, supy = ah.y + al.y;
                float vx = acc[mt][nt][half * 2 + 0];
                float vy = acc[mt][nt][half * 2 + 1];
                float ox = c0 * vx + c1 * supx;
                float oy = c0 * vy + c1 * supy;
                if (hrow_p) {
                    float2 hv = *(const float2*)(hrow_p + gc);
                    ox += hv.x; oy += hv.y;
                }
                if (bias) {
                    float2 bv = *(const float2*)(bias + gc);
                    ox += bv.x; oy += bv.y;
                }
                *(float2*)(orow_p + gc) = make_float2(fmaxf(ox, 0.f), fmaxf(oy, 0.f));
            }
        }
    }
}

// ---------------- output head + g_rowptr cleanup for next call ----------------
__global__ void k_out(const float* __restrict__ hin, const float* __restrict__ wout,
                      const float* __restrict__ bout, float* __restrict__ out)
{
    __shared__ float Wsh[DD * CC];
    __shared__ float Hsh[8][DD];
    int t = threadIdx.x;

    int gi = blockIdx.x * blockDim.x + t;
    if (gi <= NN) g_rowptr[gi] = 0;

    float4* Wsh4 = (float4*)Wsh;
    const float4* w4 = (const float4*)wout;
    #pragma unroll
    for (int i = 0; i < 8; i++) Wsh4[t + i * 256] = w4[t + i * 256];
    __syncthreads();

    int warp = t >> 5, lane = t & 31;
    int row = blockIdx.x * 8 + warp;
    if (row >= NN) return;

    ((float4*)Hsh[warp])[lane] = ((const float4*)hin)[row * 32 + lane];
    __syncwarp();

    uint64_t accp = *(const uint64_t*)&bout[2 * lane];
    const uint64_t* Wshp = (const uint64_t*)Wsh;
    #pragma unroll 4
    for (int k = 0; k < DD; k++) {
        float hv = Hsh[warp][k];
        accp = fma2(bcast2(hv), Wshp[k * 32 + lane], accp);
    }
    float2 a = unpack2(accp);
    float a0 = a.x, a1 = a.y;

    float m = fmaxf(a0, a1);
    #pragma unroll
    for (int off = 16; off; off >>= 1) m = fmaxf(m, __shfl_xor_sync(0xffffffffu, m, off));
    float se = expf(a0 - m) + expf(a1 - m);
    #pragma unroll
    for (int off = 16; off; off >>= 1) se += __shfl_xor_sync(0xffffffffu, se, off);
    float lse = m + logf(se);

    out[row * 64 + 2 * lane]     = a0 - lse;
    out[row * 64 + 2 * lane + 1] = a1 - lse;
}

// ---------------- launch ----------------
extern "C" void kernel_launch(void* const* d_in, const int* in_sizes, int n_in,
                              void* d_out, int out_size)
{
    const float* x     = (const float*)d_in[0];
    const int*   esrc  = (const int*)  d_in[1];
    const int*   edst  = (const int*)  d_in[2];
    const float* ew    = (const float*)d_in[3];
    const float* w_in  = (const float*)d_in[4];
    const float* b_in  = (const float*)d_in[5];
    const float* gcn_w = (const float*)d_in[6];
    const float* w_out = (const float*)d_in[7];
    const float* b_out = (const float*)d_in[8];
    float* out = (float*)d_out;

    cudaFuncSetAttribute(k_gemm_mma, cudaFuncAttributeMaxDynamicSharedMemorySize, MMA_SMEM);

    void *ph0v, *phAv, *phBv, *pAHv, *pALv, *pWHv, *pWLv;
    cudaGetSymbolAddress(&ph0v, g_h0);
    cudaGetSymbolAddress(&phAv, g_hA);
    cudaGetSymbolAddress(&phBv, g_hB);
    cudaGetSymbolAddress(&pAHv, g_AH);
    cudaGetSymbolAddress(&pALv, g_AL);
    cudaGetSymbolAddress(&pWHv, g_WH);
    cudaGetSymbolAddress(&pWLv, g_WL);
    float* ph0 = (float*)ph0v;
    float* phA = (float*)phAv;
    float* phB = (float*)phBv;
    __nv_bfloat16* pAH = (__nv_bfloat16*)pAHv;
    __nv_bfloat16* pAL = (__nv_bfloat16*)pALv;
    __nv_bfloat16* pWH = (__nv_bfloat16*)pWHv;
    __nv_bfloat16* pWL = (__nv_bfloat16*)pWLv;

    const int NB = (NN + 1 + 1023) / 1024; // 98

    // pre-splits (independent of CSR)
    k_wsplit<<<(5 * DD * DD + 255) / 256, 256>>>(w_in, gcn_w);
    k_xsplit<<<(NN * (DD / 2) + 255) / 256, 256>>>(x);

    // CSR build (g_rowptr zeroed by previous call's k_out; BSS-zero on first call)
    k_hist<<<(NE + 255) / 256, 256>>>(edst);
    k_scan1<<<NB, 1024>>>();
    k_scan2<<<1, 128>>>(NB);
    k_scan3<<<NB, 1024>>>();
    k_fill<<<(NE + 255) / 256, 256>>>(esrc, edst, ew);

    const int GB = (NN + 63) / 64;   // 1563 MMA blocks
    const int SB = NN / 8;           // 12500 warp-per-row blocks

    // h0 = relu(x @ w_in + b_in)   (A = x hi/lo, c1=0)
    k_gemm_mma<<<GB, 256, MMA_SMEM>>>(pAH, pAL, pWH, pWL, nullptr, b_in,
                                      ph0, 1.0f, 0.0f);

    float theta[NL];
    for (int l = 0; l < NL; l++) theta[l] = logf(0.5f / (float)(l + 2) + 1.0f);

    for (int l = 0; l < NL; l++) {
        float* hin  = (l == 0) ? ph0 : ((l & 1) ? phA : phB);
        float* hout = (l & 1) ? phB : phA;
        k_spmm<<<SB, 256>>>(hin);  // g_AH/g_AL = split(0.9*Adj@hin + 0.1*h0)
        // hout = relu(theta*(sup@W) + (1-theta)*sup + hin)
        k_gemm_mma<<<GB, 256, MMA_SMEM>>>(pAH, pAL,
                                          pWH + (size_t)(l + 1) * DD * DD,
                                          pWL + (size_t)(l + 1) * DD * DD,
                                          hin, nullptr, hout,
                                          theta[l], 1.0f - theta[l]);
    }

    // final h in g_hB (l=3 -> hout=phB)
    k_out<<<SB, 256>>>(phB, w_out, b_out, out);
}